// round 1
// baseline (speedup 1.0000x reference)
#include <cuda_runtime.h>
#include <cuda_bf16.h>

#define N_NODES 50000
#define N_EDGES 1600000
#define QM 8
#define RBF 8
#define HID 64

// Scratch accumulators (per-node segment sums). 50000*8 + 50000*24 floats = 6.4 MB.
__device__ __align__(16) float g_sum0[N_NODES * 8];
__device__ __align__(16) float g_sum1[N_NODES * 24];

// Dynamic SMEM layout (floats)
#define SW1_OFF 0          // 8*64   = 512
#define SW2_OFF 512        // 64*64  = 4096
#define SW3_OFF 4608       // 64*64  = 4096
#define SW4_OFF 8704       // 64*16  = 1024
#define HS_OFF  9728       // 64*256 = 16384
#define SMEM_FLOATS 26112
#define SMEM_BYTES (SMEM_FLOATS * 4)

__device__ __forceinline__ float silu(float x) {
    return __fdividef(x, 1.0f + __expf(-x));
}

__device__ __forceinline__ void red4(float* a, float x, float y, float z, float w) {
    asm volatile("red.global.add.v4.f32 [%0], {%1,%2,%3,%4};"
                 :: "l"(a), "f"(x), "f"(y), "f"(z), "f"(w) : "memory");
}

__global__ void __launch_bounds__(256)
edge_kernel(const float* __restrict__ ef,   // edge_feats [E,8]
            const float* __restrict__ ea,   // edge_attrs [E,4]
            const float* __restrict__ qi,   // charges_induced [N,8]
            const int*   __restrict__ eidx, // edge_index [2,E]
            const float* __restrict__ w1,
            const float* __restrict__ w2,
            const float* __restrict__ w3,
            const float* __restrict__ w4)
{
    extern __shared__ float smem[];
    float* sw1 = smem + SW1_OFF;
    float* sw2 = smem + SW2_OFF;
    float* sw3 = smem + SW3_OFF;
    float* sw4 = smem + SW4_OFF;
    float* hs  = smem + HS_OFF;

    const int tid = threadIdx.x;
    const float s8  = 0.3535533905932738f;  // 1/sqrt(8)
    const float s64 = 0.125f;               // 1/sqrt(64)

    for (int i = tid; i < 512;  i += 256) sw1[i] = w1[i] * s8;
    for (int i = tid; i < 4096; i += 256) sw2[i] = w2[i] * s64;
    for (int i = tid; i < 4096; i += 256) sw3[i] = w3[i] * s64;
    for (int i = tid; i < 1024; i += 256) sw4[i] = w4[i] * s64;
    __syncthreads();

    const int e = blockIdx.x * 256 + tid;
    if (e >= N_EDGES) return;

    // ---- Layer 1: 8 -> 64 (inputs in registers) ----
    float in8[8];
    {
        float4 a = *(const float4*)(ef + (size_t)e * 8);
        float4 b = *(const float4*)(ef + (size_t)e * 8 + 4);
        in8[0]=a.x; in8[1]=a.y; in8[2]=a.z; in8[3]=a.w;
        in8[4]=b.x; in8[5]=b.y; in8[6]=b.z; in8[7]=b.w;
    }
    float acc[64];
    #pragma unroll
    for (int j = 0; j < 64; j++) acc[j] = 0.f;
    #pragma unroll
    for (int k = 0; k < 8; k++) {
        const float hk = in8[k];
        #pragma unroll
        for (int j = 0; j < 64; j += 4) {
            float4 w = *(const float4*)(sw1 + k * 64 + j);
            acc[j+0] = fmaf(hk, w.x, acc[j+0]);
            acc[j+1] = fmaf(hk, w.y, acc[j+1]);
            acc[j+2] = fmaf(hk, w.z, acc[j+2]);
            acc[j+3] = fmaf(hk, w.w, acc[j+3]);
        }
    }
    #pragma unroll
    for (int j = 0; j < 64; j++) hs[j * 256 + tid] = silu(acc[j]);

    // ---- Layer 2: 64 -> 64 ----
    #pragma unroll
    for (int j = 0; j < 64; j++) acc[j] = 0.f;
    #pragma unroll 8
    for (int k = 0; k < 64; k++) {
        const float hk = hs[k * 256 + tid];
        #pragma unroll
        for (int j = 0; j < 64; j += 4) {
            float4 w = *(const float4*)(sw2 + k * 64 + j);
            acc[j+0] = fmaf(hk, w.x, acc[j+0]);
            acc[j+1] = fmaf(hk, w.y, acc[j+1]);
            acc[j+2] = fmaf(hk, w.z, acc[j+2]);
            acc[j+3] = fmaf(hk, w.w, acc[j+3]);
        }
    }
    #pragma unroll
    for (int j = 0; j < 64; j++) hs[j * 256 + tid] = silu(acc[j]);

    // ---- Layer 3: 64 -> 64 ----
    #pragma unroll
    for (int j = 0; j < 64; j++) acc[j] = 0.f;
    #pragma unroll 8
    for (int k = 0; k < 64; k++) {
        const float hk = hs[k * 256 + tid];
        #pragma unroll
        for (int j = 0; j < 64; j += 4) {
            float4 w = *(const float4*)(sw3 + k * 64 + j);
            acc[j+0] = fmaf(hk, w.x, acc[j+0]);
            acc[j+1] = fmaf(hk, w.y, acc[j+1]);
            acc[j+2] = fmaf(hk, w.z, acc[j+2]);
            acc[j+3] = fmaf(hk, w.w, acc[j+3]);
        }
    }
    #pragma unroll
    for (int j = 0; j < 64; j++) hs[j * 256 + tid] = silu(acc[j]);

    // ---- Layer 4: 64 -> 16 (no activation) ----
    float tp[16];
    #pragma unroll
    for (int j = 0; j < 16; j++) tp[j] = 0.f;
    #pragma unroll 8
    for (int k = 0; k < 64; k++) {
        const float hk = hs[k * 256 + tid];
        #pragma unroll
        for (int j = 0; j < 16; j += 4) {
            float4 w = *(const float4*)(sw4 + k * 16 + j);
            tp[j+0] = fmaf(hk, w.x, tp[j+0]);
            tp[j+1] = fmaf(hk, w.y, tp[j+1]);
            tp[j+2] = fmaf(hk, w.z, tp[j+2]);
            tp[j+3] = fmaf(hk, w.w, tp[j+3]);
        }
    }

    // ---- Gather + message + scatter ----
    const int s = eidx[e];
    const int r = eidx[N_EDGES + e];
    float4 q0 = *(const float4*)(qi + (size_t)s * 8);
    float4 q1 = *(const float4*)(qi + (size_t)s * 8 + 4);
    float4 at = *(const float4*)(ea + (size_t)e * 4);
    float q[8] = {q0.x, q0.y, q0.z, q0.w, q1.x, q1.y, q1.z, q1.w};

    float m0[8], m1[24];
    #pragma unroll
    for (int u = 0; u < 8; u++) {
        float wq0 = tp[u] * q[u];
        float wq1 = tp[8 + u] * q[u];
        m0[u] = wq0 * at.x;
        m1[u*3 + 0] = wq1 * at.y;
        m1[u*3 + 1] = wq1 * at.z;
        m1[u*3 + 2] = wq1 * at.w;
    }
    float* d0 = g_sum0 + (size_t)r * 8;
    red4(d0,     m0[0], m0[1], m0[2], m0[3]);
    red4(d0 + 4, m0[4], m0[5], m0[6], m0[7]);
    float* d1 = g_sum1 + (size_t)r * 24;
    #pragma unroll
    for (int i = 0; i < 24; i += 4)
        red4(d1 + i, m1[i], m1[i+1], m1[i+2], m1[i+3]);
}

// One warp per node: e0 = sum0·W0·node0, e1 = sum1·W1·node1 / sqrt(3)
__global__ void __launch_bounds__(256)
node_kernel(const float* __restrict__ nf,   // node_feats [N,256]
            const float* __restrict__ W0,   // [8,64]
            const float* __restrict__ W1,   // [8,64]
            float* __restrict__ out)
{
    __shared__ float sW0[512], sW1[512];
    const int tid = threadIdx.x;
    for (int i = tid; i < 512; i += 256) { sW0[i] = W0[i]; sW1[i] = W1[i]; }
    __syncthreads();

    const int warp = tid >> 5;
    const int lane = tid & 31;
    const int n = blockIdx.x * 8 + warp;
    if (n >= N_NODES) return;

    float s0[8];
    #pragma unroll
    for (int u = 0; u < 8; u++) s0[u] = g_sum0[(size_t)n * 8 + u];
    float s1[24];
    #pragma unroll
    for (int i = 0; i < 24; i++) s1[i] = g_sum1[(size_t)n * 24 + i];

    const float* nrow = nf + (size_t)n * 256;
    float e0 = 0.f, e1 = 0.f;
    #pragma unroll
    for (int half = 0; half < 2; half++) {
        const int v = lane + 32 * half;
        float a0 = 0.f;
        #pragma unroll
        for (int u = 0; u < 8; u++) a0 = fmaf(s0[u], sW0[u * 64 + v], a0);
        e0 = fmaf(a0, nrow[v], e0);
        #pragma unroll
        for (int k = 0; k < 3; k++) {
            float a1 = 0.f;
            #pragma unroll
            for (int u = 0; u < 8; u++) a1 = fmaf(s1[u * 3 + k], sW1[u * 64 + v], a1);
            e1 = fmaf(a1, nrow[64 + v * 3 + k], e1);
        }
    }
    float e = e0 + e1 * 0.5773502691896258f;  // 1/sqrt(3)
    #pragma unroll
    for (int o = 16; o; o >>= 1) e += __shfl_xor_sync(0xffffffffu, e, o);
    if (lane == 0) out[n] = 0.03125f * e;     // 1/sqrt(8*64*2)
}

extern "C" void kernel_launch(void* const* d_in, const int* in_sizes, int n_in,
                              void* d_out, int out_size)
{
    const float* node_feats      = (const float*)d_in[0];
    const float* charges_induced = (const float*)d_in[2];
    const float* edge_feats      = (const float*)d_in[3];
    const float* edge_attrs      = (const float*)d_in[4];
    const float* mlp_w1          = (const float*)d_in[6];
    const float* mlp_w2          = (const float*)d_in[7];
    const float* mlp_w3          = (const float*)d_in[8];
    const float* mlp_w4          = (const float*)d_in[9];
    const float* W0              = (const float*)d_in[10];
    const float* W1              = (const float*)d_in[11];
    const int*   eidx            = (const int*)d_in[12];
    float* out = (float*)d_out;

    void *p0 = nullptr, *p1 = nullptr;
    cudaGetSymbolAddress(&p0, g_sum0);
    cudaGetSymbolAddress(&p1, g_sum1);
    cudaMemsetAsync(p0, 0, (size_t)N_NODES * 8 * sizeof(float));
    cudaMemsetAsync(p1, 0, (size_t)N_NODES * 24 * sizeof(float));

    cudaFuncSetAttribute(edge_kernel, cudaFuncAttributeMaxDynamicSharedMemorySize, SMEM_BYTES);

    edge_kernel<<<N_EDGES / 256, 256, SMEM_BYTES>>>(
        edge_feats, edge_attrs, charges_induced, eidx,
        mlp_w1, mlp_w2, mlp_w3, mlp_w4);

    node_kernel<<<(N_NODES + 7) / 8, 256>>>(node_feats, W0, W1, out);
}

// round 2
// speedup vs baseline: 1.2276x; 1.2276x over previous
#include <cuda_runtime.h>
#include <cuda_bf16.h>

#define N_NODES 50000
#define N_EDGES 1600000
#define QM 8
#define RBF 8
#define HID 64

// Scratch accumulators (per-node segment sums).
__device__ __align__(16) float g_sum0[N_NODES * 8];
__device__ __align__(16) float g_sum1[N_NODES * 24];

// Dynamic SMEM layout (floats)
#define SW1_OFF 0          // 8*64   = 512
#define SW2_OFF 512        // 64*64  = 4096
#define SW3_OFF 4608       // 64*64  = 4096
#define SW4_OFF 8704       // 64*16  = 1024
#define HS_OFF  9728       // 64*256 = 16384
#define SMEM_FLOATS 26112
#define SMEM_BYTES (SMEM_FLOATS * 4)

typedef unsigned long long u64t;

__device__ __forceinline__ float silu(float x) {
    return __fdividef(x, 1.0f + __expf(-x));
}

__device__ __forceinline__ u64t pack2(float x) {
    u64t r;
    asm("mov.b64 %0, {%1, %1};" : "=l"(r) : "f"(x));
    return r;
}

__device__ __forceinline__ void unpack2(u64t v, float& lo, float& hi) {
    asm("mov.b64 {%0, %1}, %2;" : "=f"(lo), "=f"(hi) : "l"(v));
}

// d += a * b (packed 2x fp32)
__device__ __forceinline__ void fma2(u64t& d, u64t a, u64t b) {
    asm("fma.rn.f32x2 %0, %1, %2, %0;" : "+l"(d) : "l"(a), "l"(b));
}

__device__ __forceinline__ void red4(float* a, float x, float y, float z, float w) {
    asm volatile("red.global.add.v4.f32 [%0], {%1,%2,%3,%4};"
                 :: "l"(a), "f"(x), "f"(y), "f"(z), "f"(w) : "memory");
}

__global__ void __launch_bounds__(256)
edge_kernel(const float* __restrict__ ef,   // edge_feats [E,8]
            const float* __restrict__ ea,   // edge_attrs [E,4]
            const float* __restrict__ qi,   // charges_induced [N,8]
            const int*   __restrict__ eidx, // edge_index [2,E]
            const float* __restrict__ w1,
            const float* __restrict__ w2,
            const float* __restrict__ w3,
            const float* __restrict__ w4)
{
    extern __shared__ float smem[];
    float* sw1 = smem + SW1_OFF;
    float* sw2 = smem + SW2_OFF;
    float* sw3 = smem + SW3_OFF;
    float* sw4 = smem + SW4_OFF;
    float* hs  = smem + HS_OFF;

    const int tid = threadIdx.x;
    const float s8  = 0.3535533905932738f;  // 1/sqrt(8)
    const float s64 = 0.125f;               // 1/sqrt(64)

    for (int i = tid; i < 512;  i += 256) sw1[i] = w1[i] * s8;
    for (int i = tid; i < 4096; i += 256) sw2[i] = w2[i] * s64;
    for (int i = tid; i < 4096; i += 256) sw3[i] = w3[i] * s64;
    for (int i = tid; i < 1024; i += 256) sw4[i] = w4[i] * s64;
    __syncthreads();

    const int e = blockIdx.x * 256 + tid;
    if (e >= N_EDGES) return;

    // ---- Layer 1: 8 -> 64 (inputs in registers), packed f32x2 ----
    float in8[8];
    {
        float4 a = *(const float4*)(ef + (size_t)e * 8);
        float4 b = *(const float4*)(ef + (size_t)e * 8 + 4);
        in8[0]=a.x; in8[1]=a.y; in8[2]=a.z; in8[3]=a.w;
        in8[4]=b.x; in8[5]=b.y; in8[6]=b.z; in8[7]=b.w;
    }
    u64t acc[32];   // 32 packed pairs = 64 outputs
    #pragma unroll
    for (int j = 0; j < 32; j++) acc[j] = 0ull;
    #pragma unroll
    for (int k = 0; k < 8; k++) {
        const u64t hk2 = pack2(in8[k]);
        #pragma unroll
        for (int j = 0; j < 16; j++) {
            ulonglong2 w = *(const ulonglong2*)(sw1 + k * 64 + j * 4);
            fma2(acc[j*2+0], hk2, w.x);
            fma2(acc[j*2+1], hk2, w.y);
        }
    }
    #pragma unroll
    for (int j = 0; j < 32; j++) {
        float lo, hi; unpack2(acc[j], lo, hi);
        hs[(2*j+0) * 256 + tid] = silu(lo);
        hs[(2*j+1) * 256 + tid] = silu(hi);
    }

    // ---- Layer 2: 64 -> 64 ----
    #pragma unroll
    for (int j = 0; j < 32; j++) acc[j] = 0ull;
    #pragma unroll 8
    for (int k = 0; k < 64; k++) {
        const u64t hk2 = pack2(hs[k * 256 + tid]);
        #pragma unroll
        for (int j = 0; j < 16; j++) {
            ulonglong2 w = *(const ulonglong2*)(sw2 + k * 64 + j * 4);
            fma2(acc[j*2+0], hk2, w.x);
            fma2(acc[j*2+1], hk2, w.y);
        }
    }
    __syncthreads();  // all reads of hs done chipwide within thread; cheap safety for WAR
    #pragma unroll
    for (int j = 0; j < 32; j++) {
        float lo, hi; unpack2(acc[j], lo, hi);
        hs[(2*j+0) * 256 + tid] = silu(lo);
        hs[(2*j+1) * 256 + tid] = silu(hi);
    }

    // ---- Layer 3: 64 -> 64 ----
    #pragma unroll
    for (int j = 0; j < 32; j++) acc[j] = 0ull;
    #pragma unroll 8
    for (int k = 0; k < 64; k++) {
        const u64t hk2 = pack2(hs[k * 256 + tid]);
        #pragma unroll
        for (int j = 0; j < 16; j++) {
            ulonglong2 w = *(const ulonglong2*)(sw3 + k * 64 + j * 4);
            fma2(acc[j*2+0], hk2, w.x);
            fma2(acc[j*2+1], hk2, w.y);
        }
    }
    __syncthreads();
    #pragma unroll
    for (int j = 0; j < 32; j++) {
        float lo, hi; unpack2(acc[j], lo, hi);
        hs[(2*j+0) * 256 + tid] = silu(lo);
        hs[(2*j+1) * 256 + tid] = silu(hi);
    }

    // ---- Layer 4: 64 -> 16 (no activation) ----
    u64t tpp[8];
    #pragma unroll
    for (int j = 0; j < 8; j++) tpp[j] = 0ull;
    #pragma unroll 8
    for (int k = 0; k < 64; k++) {
        const u64t hk2 = pack2(hs[k * 256 + tid]);
        #pragma unroll
        for (int j = 0; j < 4; j++) {
            ulonglong2 w = *(const ulonglong2*)(sw4 + k * 16 + j * 4);
            fma2(tpp[j*2+0], hk2, w.x);
            fma2(tpp[j*2+1], hk2, w.y);
        }
    }
    float tp[16];
    #pragma unroll
    for (int j = 0; j < 8; j++) unpack2(tpp[j], tp[2*j], tp[2*j+1]);

    // ---- Gather + message + scatter ----
    const int s = eidx[e];
    const int r = eidx[N_EDGES + e];
    float4 q0 = *(const float4*)(qi + (size_t)s * 8);
    float4 q1 = *(const float4*)(qi + (size_t)s * 8 + 4);
    float4 at = *(const float4*)(ea + (size_t)e * 4);
    float q[8] = {q0.x, q0.y, q0.z, q0.w, q1.x, q1.y, q1.z, q1.w};

    float m0[8], m1[24];
    #pragma unroll
    for (int u = 0; u < 8; u++) {
        float wq0 = tp[u] * q[u];
        float wq1 = tp[8 + u] * q[u];
        m0[u] = wq0 * at.x;
        m1[u*3 + 0] = wq1 * at.y;
        m1[u*3 + 1] = wq1 * at.z;
        m1[u*3 + 2] = wq1 * at.w;
    }
    float* d0 = g_sum0 + (size_t)r * 8;
    red4(d0,     m0[0], m0[1], m0[2], m0[3]);
    red4(d0 + 4, m0[4], m0[5], m0[6], m0[7]);
    float* d1 = g_sum1 + (size_t)r * 24;
    #pragma unroll
    for (int i = 0; i < 24; i += 4)
        red4(d1 + i, m1[i], m1[i+1], m1[i+2], m1[i+3]);
}

// One warp per node: e0 = sum0·W0·node0, e1 = sum1·W1·node1 / sqrt(3)
__global__ void __launch_bounds__(256)
node_kernel(const float* __restrict__ nf,   // node_feats [N,256]
            const float* __restrict__ W0,   // [8,64]
            const float* __restrict__ W1,   // [8,64]
            float* __restrict__ out)
{
    __shared__ float sW0[512], sW1[512];
    const int tid = threadIdx.x;
    for (int i = tid; i < 512; i += 256) { sW0[i] = W0[i]; sW1[i] = W1[i]; }
    __syncthreads();

    const int warp = tid >> 5;
    const int lane = tid & 31;
    const int n = blockIdx.x * 8 + warp;
    if (n >= N_NODES) return;

    float s0[8];
    #pragma unroll
    for (int u = 0; u < 8; u++) s0[u] = g_sum0[(size_t)n * 8 + u];
    float s1[24];
    #pragma unroll
    for (int i = 0; i < 24; i++) s1[i] = g_sum1[(size_t)n * 24 + i];

    const float* nrow = nf + (size_t)n * 256;
    float e0 = 0.f, e1 = 0.f;
    #pragma unroll
    for (int half = 0; half < 2; half++) {
        const int v = lane + 32 * half;
        float a0 = 0.f;
        #pragma unroll
        for (int u = 0; u < 8; u++) a0 = fmaf(s0[u], sW0[u * 64 + v], a0);
        e0 = fmaf(a0, nrow[v], e0);
        #pragma unroll
        for (int k = 0; k < 3; k++) {
            float a1 = 0.f;
            #pragma unroll
            for (int u = 0; u < 8; u++) a1 = fmaf(s1[u * 3 + k], sW1[u * 64 + v], a1);
            e1 = fmaf(a1, nrow[64 + v * 3 + k], e1);
        }
    }
    float e = e0 + e1 * 0.5773502691896258f;  // 1/sqrt(3)
    #pragma unroll
    for (int o = 16; o; o >>= 1) e += __shfl_xor_sync(0xffffffffu, e, o);
    if (lane == 0) out[n] = 0.03125f * e;     // 1/sqrt(8*64*2)
}

extern "C" void kernel_launch(void* const* d_in, const int* in_sizes, int n_in,
                              void* d_out, int out_size)
{
    const float* node_feats      = (const float*)d_in[0];
    const float* charges_induced = (const float*)d_in[2];
    const float* edge_feats      = (const float*)d_in[3];
    const float* edge_attrs      = (const float*)d_in[4];
    const float* mlp_w1          = (const float*)d_in[6];
    const float* mlp_w2          = (const float*)d_in[7];
    const float* mlp_w3          = (const float*)d_in[8];
    const float* mlp_w4          = (const float*)d_in[9];
    const float* W0              = (const float*)d_in[10];
    const float* W1              = (const float*)d_in[11];
    const int*   eidx            = (const int*)d_in[12];
    float* out = (float*)d_out;

    void *p0 = nullptr, *p1 = nullptr;
    cudaGetSymbolAddress(&p0, g_sum0);
    cudaGetSymbolAddress(&p1, g_sum1);
    cudaMemsetAsync(p0, 0, (size_t)N_NODES * 8 * sizeof(float));
    cudaMemsetAsync(p1, 0, (size_t)N_NODES * 24 * sizeof(float));

    cudaFuncSetAttribute(edge_kernel, cudaFuncAttributeMaxDynamicSharedMemorySize, SMEM_BYTES);

    edge_kernel<<<N_EDGES / 256, 256, SMEM_BYTES>>>(
        edge_feats, edge_attrs, charges_induced, eidx,
        mlp_w1, mlp_w2, mlp_w3, mlp_w4);

    node_kernel<<<(N_NODES + 7) / 8, 256>>>(node_feats, W0, W1, out);
}

// round 3
// speedup vs baseline: 1.5029x; 1.2243x over previous
#include <cuda_runtime.h>
#include <cuda_bf16.h>

#define N_NODES 50000
#define N_EDGES 1600000

// Scratch accumulators (per-node segment sums).
__device__ __align__(16) float g_sum0[N_NODES * 8];
__device__ __align__(16) float g_sum1[N_NODES * 24];

// Dynamic SMEM layout (float offsets)
#define SW1_OFF 0          // 8*64    = 512
#define SW2_OFF 512        // 64*64   = 4096
#define SW3_OFF 4608       // 64*64   = 4096
#define SW4_OFF 8704       // 64*16   = 1024
#define X_OFF   9728       // 8*256   = 2048
#define H_OFF   11776      // 64*256  = 16384
#define SMEM_FLOATS 28160
#define SMEM_BYTES (SMEM_FLOATS * 4)   // 112640 B -> 2 CTAs/SM

typedef unsigned long long u64t;

__device__ __forceinline__ float silu(float x) {
    return __fdividef(x, 1.0f + __expf(-x));
}

__device__ __forceinline__ u64t pack2(float x) {
    u64t r;
    asm("mov.b64 %0, {%1, %1};" : "=l"(r) : "f"(x));
    return r;
}

__device__ __forceinline__ void unpack2(u64t v, float& lo, float& hi) {
    asm("mov.b64 {%0, %1}, %2;" : "=f"(lo), "=f"(hi) : "l"(v));
}

// d += a * b (packed 2x fp32)
__device__ __forceinline__ void fma2(u64t& d, u64t a, u64t b) {
    asm("fma.rn.f32x2 %0, %1, %2, %0;" : "+l"(d) : "l"(a), "l"(b));
}

__device__ __forceinline__ void red4(float* a, float x, float y, float z, float w) {
    asm volatile("red.global.add.v4.f32 [%0], {%1,%2,%3,%4};"
                 :: "l"(a), "f"(x), "f"(y), "f"(z), "f"(w) : "memory");
}

// Warp-cooperative layer: thread (lane, warp) computes edges {lane+32i} x outputs
// {8*warp + 0..7}. hin layout [K][256], hout layout [64][256]. Weights broadcast.
template<int K, bool ACT, bool SYNC_BEFORE_WRITE>
__device__ __forceinline__ void mlp_layer(const float* __restrict__ w,    // [K][64]
                                          const float* __restrict__ hin,
                                          float* __restrict__ hout,
                                          int lane, int j0)
{
    u64t acc[32];
    #pragma unroll
    for (int i = 0; i < 32; i++) acc[i] = 0ull;

    #pragma unroll 8
    for (int k = 0; k < K; k++) {
        // 8 weights for this warp's output octet: natural (w[j],w[j+1]) pairs, broadcast
        ulonglong2 wa = *(const ulonglong2*)(w + k * 64 + j0);       // w[j0..j0+3]
        ulonglong2 wb = *(const ulonglong2*)(w + k * 64 + j0 + 4);   // w[j0+4..j0+7]
        const float* hrow = hin + k * 256 + lane;
        #pragma unroll
        for (int i = 0; i < 8; i++) {
            u64t h2 = pack2(hrow[i * 32]);
            fma2(acc[i*4+0], h2, wa.x);
            fma2(acc[i*4+1], h2, wa.y);
            fma2(acc[i*4+2], h2, wb.x);
            fma2(acc[i*4+3], h2, wb.y);
        }
    }

    if (SYNC_BEFORE_WRITE) __syncthreads();  // all reads of hin complete before in-place writes

    #pragma unroll
    for (int i = 0; i < 8; i++) {
        const int m = lane + i * 32;
        #pragma unroll
        for (int jp = 0; jp < 4; jp++) {
            float lo, hi;
            unpack2(acc[i*4+jp], lo, hi);
            if (ACT) { lo = silu(lo); hi = silu(hi); }
            hout[(j0 + 2*jp + 0) * 256 + m] = lo;   // 128B-contiguous per warp: conflict-free
            hout[(j0 + 2*jp + 1) * 256 + m] = hi;
        }
    }
    __syncthreads();  // writes visible before next layer reads
}

__global__ void __launch_bounds__(256, 2)
edge_kernel(const float* __restrict__ ef,   // edge_feats [E,8]
            const float* __restrict__ ea,   // edge_attrs [E,4]
            const float* __restrict__ qi,   // charges_induced [N,8]
            const int*   __restrict__ eidx, // edge_index [2,E]
            const float* __restrict__ w1,
            const float* __restrict__ w2,
            const float* __restrict__ w3,
            const float* __restrict__ w4)
{
    extern __shared__ float smem[];
    float* sw1 = smem + SW1_OFF;
    float* sw2 = smem + SW2_OFF;
    float* sw3 = smem + SW3_OFF;
    float* sw4 = smem + SW4_OFF;
    float* xs  = smem + X_OFF;
    float* hs  = smem + H_OFF;

    const int tid  = threadIdx.x;
    const int lane = tid & 31;
    const int j0   = (tid >> 5) * 8;
    const float s8  = 0.3535533905932738f;  // 1/sqrt(8)
    const float s64 = 0.125f;               // 1/sqrt(64)

    for (int i = tid; i < 512;  i += 256) sw1[i] = w1[i] * s8;
    for (int i = tid; i < 4096; i += 256) sw2[i] = w2[i] * s64;
    for (int i = tid; i < 4096; i += 256) sw3[i] = w3[i] * s64;
    for (int i = tid; i < 1024; i += 256) sw4[i] = w4[i] * s64;

    // Stage this block's edge features transposed: xs[k][m]
    const int e = blockIdx.x * 256 + tid;
    {
        float4 a = *(const float4*)(ef + (size_t)e * 8);
        float4 b = *(const float4*)(ef + (size_t)e * 8 + 4);
        xs[0*256 + tid] = a.x; xs[1*256 + tid] = a.y;
        xs[2*256 + tid] = a.z; xs[3*256 + tid] = a.w;
        xs[4*256 + tid] = b.x; xs[5*256 + tid] = b.y;
        xs[6*256 + tid] = b.z; xs[7*256 + tid] = b.w;
    }
    __syncthreads();

    mlp_layer<8,  true, false>(sw1, xs, hs, lane, j0);  // 8  -> 64 (distinct buffers)
    mlp_layer<64, true, true >(sw2, hs, hs, lane, j0);  // 64 -> 64 in place
    mlp_layer<64, true, true >(sw3, hs, hs, lane, j0);  // 64 -> 64 in place

    // ---- Layer 4: 64 -> 16, per-edge-thread (no activation) ----
    u64t tpp[8];
    #pragma unroll
    for (int j = 0; j < 8; j++) tpp[j] = 0ull;
    #pragma unroll 8
    for (int k = 0; k < 64; k++) {
        const u64t hk2 = pack2(hs[k * 256 + tid]);
        ulonglong2 wA = *(const ulonglong2*)(sw4 + k * 16);
        ulonglong2 wB = *(const ulonglong2*)(sw4 + k * 16 + 4);
        ulonglong2 wC = *(const ulonglong2*)(sw4 + k * 16 + 8);
        ulonglong2 wD = *(const ulonglong2*)(sw4 + k * 16 + 12);
        fma2(tpp[0], hk2, wA.x); fma2(tpp[1], hk2, wA.y);
        fma2(tpp[2], hk2, wB.x); fma2(tpp[3], hk2, wB.y);
        fma2(tpp[4], hk2, wC.x); fma2(tpp[5], hk2, wC.y);
        fma2(tpp[6], hk2, wD.x); fma2(tpp[7], hk2, wD.y);
    }
    float tp[16];
    #pragma unroll
    for (int j = 0; j < 8; j++) unpack2(tpp[j], tp[2*j], tp[2*j+1]);

    // ---- Gather + message + scatter ----
    const int s = eidx[e];
    const int r = eidx[N_EDGES + e];
    float4 q0 = *(const float4*)(qi + (size_t)s * 8);
    float4 q1 = *(const float4*)(qi + (size_t)s * 8 + 4);
    float4 at = *(const float4*)(ea + (size_t)e * 4);
    float q[8] = {q0.x, q0.y, q0.z, q0.w, q1.x, q1.y, q1.z, q1.w};

    float m0[8], m1[24];
    #pragma unroll
    for (int u = 0; u < 8; u++) {
        float wq0 = tp[u] * q[u];
        float wq1 = tp[8 + u] * q[u];
        m0[u] = wq0 * at.x;
        m1[u*3 + 0] = wq1 * at.y;
        m1[u*3 + 1] = wq1 * at.z;
        m1[u*3 + 2] = wq1 * at.w;
    }
    float* d0 = g_sum0 + (size_t)r * 8;
    red4(d0,     m0[0], m0[1], m0[2], m0[3]);
    red4(d0 + 4, m0[4], m0[5], m0[6], m0[7]);
    float* d1 = g_sum1 + (size_t)r * 24;
    #pragma unroll
    for (int i = 0; i < 24; i += 4)
        red4(d1 + i, m1[i], m1[i+1], m1[i+2], m1[i+3]);
}

// One warp per node: e0 = sum0·W0·node0, e1 = sum1·W1·node1 / sqrt(3)
__global__ void __launch_bounds__(256)
node_kernel(const float* __restrict__ nf,   // node_feats [N,256]
            const float* __restrict__ W0,   // [8,64]
            const float* __restrict__ W1,   // [8,64]
            float* __restrict__ out)
{
    __shared__ float sW0[512], sW1[512];
    const int tid = threadIdx.x;
    for (int i = tid; i < 512; i += 256) { sW0[i] = W0[i]; sW1[i] = W1[i]; }
    __syncthreads();

    const int warp = tid >> 5;
    const int lane = tid & 31;
    const int n = blockIdx.x * 8 + warp;
    if (n >= N_NODES) return;

    float s0[8];
    #pragma unroll
    for (int u = 0; u < 8; u++) s0[u] = g_sum0[(size_t)n * 8 + u];
    float s1[24];
    #pragma unroll
    for (int i = 0; i < 24; i++) s1[i] = g_sum1[(size_t)n * 24 + i];

    const float* nrow = nf + (size_t)n * 256;
    float e0 = 0.f, e1 = 0.f;
    #pragma unroll
    for (int half = 0; half < 2; half++) {
        const int v = lane + 32 * half;
        float a0 = 0.f;
        #pragma unroll
        for (int u = 0; u < 8; u++) a0 = fmaf(s0[u], sW0[u * 64 + v], a0);
        e0 = fmaf(a0, nrow[v], e0);
        #pragma unroll
        for (int k = 0; k < 3; k++) {
            float a1 = 0.f;
            #pragma unroll
            for (int u = 0; u < 8; u++) a1 = fmaf(s1[u * 3 + k], sW1[u * 64 + v], a1);
            e1 = fmaf(a1, nrow[64 + v * 3 + k], e1);
        }
    }
    float e = e0 + e1 * 0.5773502691896258f;  // 1/sqrt(3)
    #pragma unroll
    for (int o = 16; o; o >>= 1) e += __shfl_xor_sync(0xffffffffu, e, o);
    if (lane == 0) out[n] = 0.03125f * e;     // 1/sqrt(8*64*2)
}

extern "C" void kernel_launch(void* const* d_in, const int* in_sizes, int n_in,
                              void* d_out, int out_size)
{
    const float* node_feats      = (const float*)d_in[0];
    const float* charges_induced = (const float*)d_in[2];
    const float* edge_feats      = (const float*)d_in[3];
    const float* edge_attrs      = (const float*)d_in[4];
    const float* mlp_w1          = (const float*)d_in[6];
    const float* mlp_w2          = (const float*)d_in[7];
    const float* mlp_w3          = (const float*)d_in[8];
    const float* mlp_w4          = (const float*)d_in[9];
    const float* W0              = (const float*)d_in[10];
    const float* W1              = (const float*)d_in[11];
    const int*   eidx            = (const int*)d_in[12];
    float* out = (float*)d_out;

    void *p0 = nullptr, *p1 = nullptr;
    cudaGetSymbolAddress(&p0, g_sum0);
    cudaGetSymbolAddress(&p1, g_sum1);
    cudaMemsetAsync(p0, 0, (size_t)N_NODES * 8 * sizeof(float));
    cudaMemsetAsync(p1, 0, (size_t)N_NODES * 24 * sizeof(float));

    cudaFuncSetAttribute(edge_kernel, cudaFuncAttributeMaxDynamicSharedMemorySize, SMEM_BYTES);

    edge_kernel<<<N_EDGES / 256, 256, SMEM_BYTES>>>(
        edge_feats, edge_attrs, charges_induced, eidx,
        mlp_w1, mlp_w2, mlp_w3, mlp_w4);

    node_kernel<<<(N_NODES + 7) / 8, 256>>>(node_feats, W0, W1, out);
}

// round 4
// speedup vs baseline: 2.6196x; 1.7431x over previous
#include <cuda_runtime.h>

#define N_NODES 50000
#define N_EDGES 1600000

// Scratch accumulators (per-node segment sums).
__device__ __align__(16) float g_sum0[N_NODES * 8];
__device__ __align__(16) float g_sum1[N_NODES * 24];

// SMEM layout (float offsets)
#define WF1_OFF 0        // 1*8*64  = 512   (layer1 B frags)
#define WF2_OFF 512      // 8*8*64  = 4096
#define WF3_OFF 4608     // 8*8*64  = 4096
#define WF4_OFF 8704     // 8*2*64  = 1024
#define H_OFF   9728     // 64*268  = 17152 (activations, edge-column-major)
#define H_STR   268      // stride mod 32 == 12 -> conflict-free A loads AND D stores
#define SMEM_FLOATS (H_OFF + 64 * H_STR)
#define SMEM_BYTES (SMEM_FLOATS * 4)   // 107,520 B -> 2 CTAs/SM

__device__ __forceinline__ float silu(float x) {
    return __fdividef(x, 1.0f + __expf(-x));
}

__device__ __forceinline__ float to_tf32(float x) {
    unsigned r;
    asm("cvt.rna.tf32.f32 %0, %1;" : "=r"(r) : "f"(x));
    return __uint_as_float(r);
}

__device__ __forceinline__ void mma_tf32(float* d, const unsigned* a, const unsigned* b) {
    asm volatile(
        "mma.sync.aligned.m16n8k8.row.col.f32.tf32.tf32.f32 "
        "{%0,%1,%2,%3}, {%4,%5,%6,%7}, {%8,%9}, {%0,%1,%2,%3};"
        : "+f"(d[0]), "+f"(d[1]), "+f"(d[2]), "+f"(d[3])
        : "r"(a[0]), "r"(a[1]), "r"(a[2]), "r"(a[3]), "r"(b[0]), "r"(b[1]));
}

__device__ __forceinline__ void red4(float* a, float x, float y, float z, float w) {
    asm volatile("red.global.add.v4.f32 [%0], {%1,%2,%3,%4};"
                 :: "l"(a), "f"(x), "f"(y), "f"(z), "f"(w) : "memory");
}

// Fill fragment-ordered weights: dst[(kt*NT+nt)*64 + lane*2 + half] =
//   tf32(w[kt*8 + (lane&3) + half*4][nt*8 + (lane>>2)] * scale)
__device__ __forceinline__ void fill_frags(float* dst, const float* __restrict__ w,
                                           int KT, int NT, int ncols, float scale, int tid) {
    const int total = KT * NT * 64;
    for (int idx = tid; idx < total; idx += 256) {
        int fi = idx >> 6, r = idx & 63;
        int lane = r >> 1, half = r & 1;
        int kt = fi / NT, nt = fi - kt * NT;
        int k = kt * 8 + (lane & 3) + half * 4;
        int n = nt * 8 + (lane >> 2);
        dst[idx] = to_tf32(w[k * ncols + n] * scale);
    }
}

// One MMA layer: warp computes its 32-edge stripe x (NT*8) outputs over KT*8 K.
// A read from h rows [0, KT*8); result accumulated into acc[2*NT][4].
template<int KT, int NT>
__device__ __forceinline__ void mma_layer(const float* __restrict__ wf,
                                          const float* __restrict__ h,
                                          int m0, int lane, float acc[][4]) {
    const int c = lane & 3, g = lane >> 2;
    #pragma unroll
    for (int kt = 0; kt < KT; kt++) {
        unsigned a[2][4];
        #pragma unroll
        for (int t = 0; t < 2; t++) {
            const float* base = h + (kt * 8 + c) * H_STR + m0 + 16 * t + g;
            a[t][0] = __float_as_uint(base[0]);
            a[t][1] = __float_as_uint(base[8]);
            a[t][2] = __float_as_uint(base[4 * H_STR]);
            a[t][3] = __float_as_uint(base[4 * H_STR + 8]);
        }
        #pragma unroll
        for (int nt = 0; nt < NT; nt++) {
            float2 bb = *(const float2*)(wf + (kt * NT + nt) * 64 + lane * 2);
            unsigned b[2] = { __float_as_uint(bb.x), __float_as_uint(bb.y) };
            mma_tf32(acc[0 * NT + nt], a[0], b);
            mma_tf32(acc[1 * NT + nt], a[1], b);
        }
    }
}

// Store D frags to h with silu + tf32 conversion (next layer's A).
template<int NT, bool ACT>
__device__ __forceinline__ void store_acts(float* __restrict__ h, int m0, int lane,
                                           float acc[][4]) {
    const int c = lane & 3, g = lane >> 2;
    __syncwarp();   // all A reads of this warp complete before in-place writes
    #pragma unroll
    for (int t = 0; t < 2; t++) {
        #pragma unroll
        for (int nt = 0; nt < NT; nt++) {
            float* a4 = acc[t * NT + nt];
            float v0 = a4[0], v1 = a4[1], v2 = a4[2], v3 = a4[3];
            if (ACT) { v0 = silu(v0); v1 = silu(v1); v2 = silu(v2); v3 = silu(v3); }
            float* p = h + (nt * 8 + 2 * c) * H_STR + m0 + 16 * t + g;
            if (ACT) {
                p[0]         = to_tf32(v0);  // row g,   col 2c
                p[H_STR]     = to_tf32(v1);  // row g,   col 2c+1
                p[8]         = to_tf32(v2);  // row g+8, col 2c
                p[H_STR + 8] = to_tf32(v3);
            } else {
                p[0] = v0; p[H_STR] = v1; p[8] = v2; p[H_STR + 8] = v3;
            }
        }
    }
    __syncwarp();   // writes visible to all lanes of this warp
}

__global__ void __launch_bounds__(256, 2)
edge_kernel(const float* __restrict__ ef,   // edge_feats [E,8]
            const float* __restrict__ ea,   // edge_attrs [E,4]
            const float* __restrict__ qi,   // charges_induced [N,8]
            const int*   __restrict__ eidx, // edge_index [2,E]
            const float* __restrict__ w1,
            const float* __restrict__ w2,
            const float* __restrict__ w3,
            const float* __restrict__ w4)
{
    extern __shared__ float smem[];
    float* wf1 = smem + WF1_OFF;
    float* wf2 = smem + WF2_OFF;
    float* wf3 = smem + WF3_OFF;
    float* wf4 = smem + WF4_OFF;
    float* h   = smem + H_OFF;

    const int tid  = threadIdx.x;
    const int lane = tid & 31;
    const int m0   = (tid >> 5) * 32;       // warp's edge-column stripe
    const float s8  = 0.3535533905932738f;  // 1/sqrt(8)
    const float s64 = 0.125f;               // 1/sqrt(64)

    fill_frags(wf1, w1, 1, 8, 64, s8,  tid);
    fill_frags(wf2, w2, 8, 8, 64, s64, tid);
    fill_frags(wf3, w3, 8, 8, 64, s64, tid);
    fill_frags(wf4, w4, 8, 2, 16, s64, tid);

    // Stage edge features (layer-1 A): h[f][col=tid], tf32-rounded
    const int e = blockIdx.x * 256 + tid;
    {
        float4 a4 = *(const float4*)(ef + (size_t)e * 8);
        float4 b4 = *(const float4*)(ef + (size_t)e * 8 + 4);
        h[0 * H_STR + tid] = to_tf32(a4.x);
        h[1 * H_STR + tid] = to_tf32(a4.y);
        h[2 * H_STR + tid] = to_tf32(a4.z);
        h[3 * H_STR + tid] = to_tf32(a4.w);
        h[4 * H_STR + tid] = to_tf32(b4.x);
        h[5 * H_STR + tid] = to_tf32(b4.y);
        h[6 * H_STR + tid] = to_tf32(b4.z);
        h[7 * H_STR + tid] = to_tf32(b4.w);
    }
    __syncthreads();   // weight frags visible block-wide (h cols are warp-private)

    float acc[16][4];

    // Layer 1: 8 -> 64
    #pragma unroll
    for (int i = 0; i < 16; i++) { acc[i][0]=0.f; acc[i][1]=0.f; acc[i][2]=0.f; acc[i][3]=0.f; }
    mma_layer<1, 8>(wf1, h, m0, lane, acc);
    store_acts<8, true>(h, m0, lane, acc);

    // Layer 2: 64 -> 64
    #pragma unroll
    for (int i = 0; i < 16; i++) { acc[i][0]=0.f; acc[i][1]=0.f; acc[i][2]=0.f; acc[i][3]=0.f; }
    mma_layer<8, 8>(wf2, h, m0, lane, acc);
    store_acts<8, true>(h, m0, lane, acc);

    // Layer 3: 64 -> 64
    #pragma unroll
    for (int i = 0; i < 16; i++) { acc[i][0]=0.f; acc[i][1]=0.f; acc[i][2]=0.f; acc[i][3]=0.f; }
    mma_layer<8, 8>(wf3, h, m0, lane, acc);
    store_acts<8, true>(h, m0, lane, acc);

    // Layer 4: 64 -> 16 (no activation, full fp32 result into h rows 0..15)
    #pragma unroll
    for (int i = 0; i < 4; i++) { acc[i][0]=0.f; acc[i][1]=0.f; acc[i][2]=0.f; acc[i][3]=0.f; }
    mma_layer<8, 2>(wf4, h, m0, lane, acc);
    store_acts<2, false>(h, m0, lane, acc);

    // Gather per-edge tp[16] from h (column reads, conflict-free)
    float tp[16];
    #pragma unroll
    for (int j = 0; j < 16; j++) tp[j] = h[j * H_STR + tid];

    // ---- Gather + message + scatter ----
    const int s = eidx[e];
    const int r = eidx[N_EDGES + e];
    float4 q0 = *(const float4*)(qi + (size_t)s * 8);
    float4 q1 = *(const float4*)(qi + (size_t)s * 8 + 4);
    float4 at = *(const float4*)(ea + (size_t)e * 4);
    float q[8] = {q0.x, q0.y, q0.z, q0.w, q1.x, q1.y, q1.z, q1.w};

    float m0v[8], m1v[24];
    #pragma unroll
    for (int u = 0; u < 8; u++) {
        float wq0 = tp[u] * q[u];
        float wq1 = tp[8 + u] * q[u];
        m0v[u] = wq0 * at.x;
        m1v[u*3 + 0] = wq1 * at.y;
        m1v[u*3 + 1] = wq1 * at.z;
        m1v[u*3 + 2] = wq1 * at.w;
    }
    float* d0 = g_sum0 + (size_t)r * 8;
    red4(d0,     m0v[0], m0v[1], m0v[2], m0v[3]);
    red4(d0 + 4, m0v[4], m0v[5], m0v[6], m0v[7]);
    float* d1 = g_sum1 + (size_t)r * 24;
    #pragma unroll
    for (int i = 0; i < 24; i += 4)
        red4(d1 + i, m1v[i], m1v[i+1], m1v[i+2], m1v[i+3]);
}

// One warp per node: e0 = sum0·W0·node0, e1 = sum1·W1·node1 / sqrt(3)
__global__ void __launch_bounds__(256)
node_kernel(const float* __restrict__ nf,   // node_feats [N,256]
            const float* __restrict__ W0,   // [8,64]
            const float* __restrict__ W1,   // [8,64]
            float* __restrict__ out)
{
    __shared__ float sW0[512], sW1[512];
    const int tid = threadIdx.x;
    for (int i = tid; i < 512; i += 256) { sW0[i] = W0[i]; sW1[i] = W1[i]; }
    __syncthreads();

    const int warp = tid >> 5;
    const int lane = tid & 31;
    const int n = blockIdx.x * 8 + warp;
    if (n >= N_NODES) return;

    float s0[8];
    #pragma unroll
    for (int u = 0; u < 8; u++) s0[u] = g_sum0[(size_t)n * 8 + u];
    float s1[24];
    #pragma unroll
    for (int i = 0; i < 24; i++) s1[i] = g_sum1[(size_t)n * 24 + i];

    const float* nrow = nf + (size_t)n * 256;
    float e0 = 0.f, e1 = 0.f;
    #pragma unroll
    for (int half = 0; half < 2; half++) {
        const int v = lane + 32 * half;
        float a0 = 0.f;
        #pragma unroll
        for (int u = 0; u < 8; u++) a0 = fmaf(s0[u], sW0[u * 64 + v], a0);
        e0 = fmaf(a0, nrow[v], e0);
        #pragma unroll
        for (int k = 0; k < 3; k++) {
            float a1 = 0.f;
            #pragma unroll
            for (int u = 0; u < 8; u++) a1 = fmaf(s1[u * 3 + k], sW1[u * 64 + v], a1);
            e1 = fmaf(a1, nrow[64 + v * 3 + k], e1);
        }
    }
    float e = e0 + e1 * 0.5773502691896258f;  // 1/sqrt(3)
    #pragma unroll
    for (int o = 16; o; o >>= 1) e += __shfl_xor_sync(0xffffffffu, e, o);
    if (lane == 0) out[n] = 0.03125f * e;     // 1/sqrt(8*64*2)
}

extern "C" void kernel_launch(void* const* d_in, const int* in_sizes, int n_in,
                              void* d_out, int out_size)
{
    const float* node_feats      = (const float*)d_in[0];
    const float* charges_induced = (const float*)d_in[2];
    const float* edge_feats      = (const float*)d_in[3];
    const float* edge_attrs      = (const float*)d_in[4];
    const float* mlp_w1          = (const float*)d_in[6];
    const float* mlp_w2          = (const float*)d_in[7];
    const float* mlp_w3          = (const float*)d_in[8];
    const float* mlp_w4          = (const float*)d_in[9];
    const float* W0              = (const float*)d_in[10];
    const float* W1              = (const float*)d_in[11];
    const int*   eidx            = (const int*)d_in[12];
    float* out = (float*)d_out;

    void *p0 = nullptr, *p1 = nullptr;
    cudaGetSymbolAddress(&p0, g_sum0);
    cudaGetSymbolAddress(&p1, g_sum1);
    cudaMemsetAsync(p0, 0, (size_t)N_NODES * 8 * sizeof(float));
    cudaMemsetAsync(p1, 0, (size_t)N_NODES * 24 * sizeof(float));

    cudaFuncSetAttribute(edge_kernel, cudaFuncAttributeMaxDynamicSharedMemorySize, SMEM_BYTES);

    edge_kernel<<<N_EDGES / 256, 256, SMEM_BYTES>>>(
        edge_feats, edge_attrs, charges_induced, eidx,
        mlp_w1, mlp_w2, mlp_w3, mlp_w4);

    node_kernel<<<(N_NODES + 7) / 8, 256>>>(node_feats, W0, W1, out);
}